// round 15
// baseline (speedup 1.0000x reference)
#include <cuda_runtime.h>
#include <math.h>

// Problem constants (fixed shapes from reference setup_inputs)
#define BB 32
#define SS 64
#define HH 256
#define CELLS_PER_BATCH (SS * SS)   // 4096
#define NBLOCKS (BB * 32)           // 1024: 32 blocks per batch
#define EPSF 1e-8f

// Per-block partial sums. Written unconditionally by every block each launch,
// so they never need zero-initialization (graph-replay safe).
__device__ float g_part_p[NBLOCKS];
__device__ float g_part_n[NBLOCKS];
// Completion counter; last block resets it so every graph replay sees 0.
__device__ unsigned int g_done;

// ---------------------------------------------------------------------------
// Single fused kernel, HALF-WARP-PER-CELL layout.
//   grid = 1024 blocks x 256 threads; block bi handles batch bi>>5.
//   Warp w owns 16 consecutive cells, processed as 8 pairs: half-warp h
//   handles cell 2i+h of the pair. Each lane loads 4 float4 (16 floats) of
//   the 256-dim vector -> 4 independent LDG.128 in flight per cell, and the
//   dot-product reduce is only 4 shuffle levels (within the 16-lane half).
// ---------------------------------------------------------------------------
__global__ void __launch_bounds__(256) cl_fused_kernel(
    const float* __restrict__ tmap,
    const float* __restrict__ pos_query,
    const int*   __restrict__ mpos,
    const int*   __restrict__ mneg,
    float*       __restrict__ out)
{
    const int b        = blockIdx.x >> 5;        // 32 blocks per batch
    const int blk_in_b = blockIdx.x & 31;
    const int wid      = threadIdx.x >> 5;
    const int lane     = threadIdx.x & 31;
    const int half     = lane >> 4;              // 0 or 1: which cell of the pair
    const int sub      = lane & 15;              // lane within the half

    // This warp's 16 consecutive cells within batch b
    const int cell0 = b * CELLS_PER_BATCH + blk_in_b * 128 + wid * 16;

    // Query: each half covers the FULL 256-dim vector (16 lanes x 4 float4).
    const float4* qp = reinterpret_cast<const float4*>(pos_query + (size_t)b * HH);
    float4 q[4];
    #pragma unroll
    for (int j = 0; j < 4; j++) q[j] = qp[sub + 16 * j];

    // ||q||^2 reduced within the half (covers whole vector) -> invq in all lanes
    float qq = 0.0f;
    #pragma unroll
    for (int j = 0; j < 4; j++)
        qq += q[j].x * q[j].x + q[j].y * q[j].y + q[j].z * q[j].z + q[j].w * q[j].w;
    #pragma unroll
    for (int o = 8; o > 0; o >>= 1)
        qq += __shfl_xor_sync(0xFFFFFFFFu, qq, o);
    const float invq = 1.0f / (sqrtf(qq) + EPSF);

    float psum = 0.0f, nsum = 0.0f;

    #pragma unroll 2
    for (int i = 0; i < 8; i++) {
        const int c  = cell0 + 2 * i + half;     // this half's cell
        const int pm = mpos[c];
        const int nm = mneg[c];
        const bool live = (pm | nm) != 0;
        if (!__any_sync(0xFFFFFFFFu, live)) continue;   // both cells dead

        float dq = 0.0f, dt = 1.0f;
        if (live) {
            const float4* tp = reinterpret_cast<const float4*>(tmap + (size_t)c * HH);
            float4 t0 = tp[sub];
            float4 t1 = tp[sub + 16];
            float4 t2 = tp[sub + 32];
            float4 t3 = tp[sub + 48];
            dq = t0.x * q[0].x + t0.y * q[0].y + t0.z * q[0].z + t0.w * q[0].w
               + t1.x * q[1].x + t1.y * q[1].y + t1.z * q[1].z + t1.w * q[1].w
               + t2.x * q[2].x + t2.y * q[2].y + t2.z * q[2].z + t2.w * q[2].w
               + t3.x * q[3].x + t3.y * q[3].y + t3.z * q[3].z + t3.w * q[3].w;
            dt = t0.x * t0.x + t0.y * t0.y + t0.z * t0.z + t0.w * t0.w
               + t1.x * t1.x + t1.y * t1.y + t1.z * t1.z + t1.w * t1.w
               + t2.x * t2.x + t2.y * t2.y + t2.z * t2.z + t2.w * t2.w
               + t3.x * t3.x + t3.y * t3.y + t3.z * t3.z + t3.w * t3.w;
        }

        // 4-level reduce within each 16-lane half (both cells reduce in parallel)
        #pragma unroll
        for (int o = 8; o > 0; o >>= 1) {
            dq += __shfl_xor_sync(0xFFFFFFFFu, dq, o);
            dt += __shfl_xor_sync(0xFFFFFFFFu, dt, o);
        }

        // s = dot(t,q)/||t||/(||q||+eps); the reference's inner renormalize
        // (||u||+eps, ||u||~=1) perturbs s by ~1e-7 << tolerance. TAO = 1.0.
        if (live && sub == 0) {
            const float e = expf(dq * rsqrtf(dt) * invq);
            if (pm) psum += e;
            if (nm) nsum += e;
        }
    }

    // Merge the two halves' accumulators (only lanes 0 and 16 are nonzero)
    psum += __shfl_xor_sync(0xFFFFFFFFu, psum, 16);
    nsum += __shfl_xor_sync(0xFFFFFFFFu, nsum, 16);

    // Block reduction -> per-block partial (unconditional write: no init needed)
    __shared__ float s_p[8];
    __shared__ float s_n[8];
    if (lane == 0) { s_p[wid] = psum; s_n[wid] = nsum; }
    __syncthreads();

    __shared__ bool s_last;
    if (threadIdx.x == 0) {
        float ap = 0.0f, an = 0.0f;
        #pragma unroll
        for (int i = 0; i < 8; i++) { ap += s_p[i]; an += s_n[i]; }
        g_part_p[blockIdx.x] = ap;
        g_part_n[blockIdx.x] = an;
        __threadfence();                          // partials visible before count
        unsigned int prev = atomicAdd(&g_done, 1u);
        s_last = (prev == NBLOCKS - 1u);
    }
    __syncthreads();
    if (!s_last) return;

    // ---- Last block: per-batch loss + average ----
    __threadfence();                              // acquire all partials
    // Warp w handles batches w, w+8, w+16, w+24; lane reads one block partial.
    float li_acc = 0.0f;
    int   v_acc  = 0;
    #pragma unroll
    for (int r = 0; r < 4; r++) {
        const int bb = wid + r * 8;
        float p = g_part_p[bb * 32 + lane];
        float n = g_part_n[bb * 32 + lane];
        #pragma unroll
        for (int o = 16; o > 0; o >>= 1) {
            p += __shfl_xor_sync(0xFFFFFFFFu, p, o);
            n += __shfl_xor_sync(0xFFFFFFFFu, n, o);
        }
        // valid(b) = nonempty pos & neg sets <=> both sums > 0 (exp > 0)
        if (lane == 0 && p > 0.0f && n > 0.0f) {
            li_acc += -logf(p / (p + n + EPSF));
            v_acc  += 1;
        }
    }
    __shared__ float s_li[8];
    __shared__ int   s_v[8];
    if (lane == 0) { s_li[wid] = li_acc; s_v[wid] = v_acc; }
    __syncthreads();
    if (threadIdx.x == 0) {
        float li = 0.0f; int v = 0;
        #pragma unroll
        for (int i = 0; i < 8; i++) { li += s_li[i]; v += s_v[i]; }
        out[0] = li / (float)(v > 0 ? v : 1);
        g_done = 0u;                              // reset for next graph replay
    }
}

// ---------------------------------------------------------------------------
// Launch. Input order (metadata / setup_inputs dict order):
//   d_in[0] = pos_query  (B,H)     float32
//   d_in[1] = tmap       (B,S,S,H) float32
//   d_in[2] = mask2d_pos (B,S,S)   bool -> int32
//   d_in[3] = mask2d_neg (B,S,S)   bool -> int32
// Output: scalar float32.
// ---------------------------------------------------------------------------
extern "C" void kernel_launch(void* const* d_in, const int* in_sizes, int n_in,
                              void* d_out, int out_size) {
    (void)in_sizes; (void)n_in; (void)out_size;
    const float* pos_query = (const float*)d_in[0];
    const float* tmap      = (const float*)d_in[1];
    const int*   mpos      = (const int*)d_in[2];
    const int*   mneg      = (const int*)d_in[3];
    float*       out       = (float*)d_out;

    cl_fused_kernel<<<NBLOCKS, 256>>>(tmap, pos_query, mpos, mneg, out);
}

// round 16
// speedup vs baseline: 1.0204x; 1.0204x over previous
#include <cuda_runtime.h>
#include <math.h>

// Problem constants (fixed shapes from reference setup_inputs)
#define BB 32
#define SS 64
#define HH 256
#define CELLS_PER_BATCH (SS * SS)   // 4096
#define NBLOCKS (BB * 32)           // 1024: 32 blocks per batch
#define EPSF 1e-8f
#define FULL 0xFFFFFFFFu

// Per-block partial sums. Written unconditionally by every block every launch,
// so they never need zero-initialization (graph-replay safe).
__device__ float g_part_p[NBLOCKS];
__device__ float g_part_n[NBLOCKS];

// ---------------------------------------------------------------------------
// Kernel 1: main reduction. Half-warp-per-cell + ballot-compacted live loop.
//   grid = 1024 blocks x 256 threads; block bi -> batch bi>>5;
//   warp w owns 16 consecutive cells.
//   - masks for all 16 cells read up front (1 lane each) -> 16-bit bitmaps;
//     the compacted loop body has NO load->branch dependence, so consecutive
//     pairs' tmap loads can be batched by the compiler (high MLP).
//   - each 16-lane half processes one live cell: 4 LDG.128 in flight,
//     4-level shuffle reduce.
//   - invq computed per-warp from q registers (no init kernel).
// ---------------------------------------------------------------------------
__global__ void __launch_bounds__(256) cl_main_kernel(
    const float* __restrict__ tmap,
    const float* __restrict__ pos_query,
    const int*   __restrict__ mpos,
    const int*   __restrict__ mneg)
{
    const int b        = blockIdx.x >> 5;        // 32 blocks per batch
    const int blk_in_b = blockIdx.x & 31;
    const int wid      = threadIdx.x >> 5;
    const int lane     = threadIdx.x & 31;
    const int half     = lane >> 4;              // which cell of each live pair
    const int sub      = lane & 15;              // lane within the half

    const int cell0 = b * CELLS_PER_BATCH + blk_in_b * 128 + wid * 16;

    // Query: each half covers the FULL 256-dim vector (16 lanes x 4 float4).
    const float4* qp = reinterpret_cast<const float4*>(pos_query + (size_t)b * HH);
    float4 q[4];
    #pragma unroll
    for (int j = 0; j < 4; j++) q[j] = qp[sub + 16 * j];

    // invq = 1/(||q||+eps): reduce within the half (covers whole vector)
    float qq = 0.0f;
    #pragma unroll
    for (int j = 0; j < 4; j++)
        qq += q[j].x * q[j].x + q[j].y * q[j].y + q[j].z * q[j].z + q[j].w * q[j].w;
    #pragma unroll
    for (int o = 8; o > 0; o >>= 1)
        qq += __shfl_xor_sync(FULL, qq, o);
    const float invq = 1.0f / (sqrtf(qq) + EPSF);

    // Read all 16 cell masks up front: lane k (k<16) covers cell0+k.
    int pmv = 0, nmv = 0;
    if (lane < 16) {
        pmv = mpos[cell0 + lane];
        nmv = mneg[cell0 + lane];
    }
    const unsigned posmask = __ballot_sync(FULL, pmv != 0);   // bits 0..15 only
    const unsigned negmask = __ballot_sync(FULL, nmv != 0);
    const unsigned livemask = posmask | negmask;
    const int nlive  = __popc(livemask);
    const int npairs = (nlive + 1) >> 1;

    float psum = 0.0f, nsum = 0.0f;

    #pragma unroll 2
    for (int i = 0; i < npairs; i++) {
        const int ord  = 2 * i + half;                     // which live cell (ordinal)
        const bool live = (ord < nlive);
        const unsigned bitpos = __fns(livemask, 0, ord + 1);  // 0xFFFFFFFF if none
        const int bit  = (int)(bitpos & 15u);              // safe index even if dead
        const int c    = cell0 + bit;

        float dq = 0.0f, dt = 1.0f;
        if (live) {
            const float4* tp = reinterpret_cast<const float4*>(tmap + (size_t)c * HH);
            float4 t0 = tp[sub];
            float4 t1 = tp[sub + 16];
            float4 t2 = tp[sub + 32];
            float4 t3 = tp[sub + 48];
            dq = t0.x * q[0].x + t0.y * q[0].y + t0.z * q[0].z + t0.w * q[0].w
               + t1.x * q[1].x + t1.y * q[1].y + t1.z * q[1].z + t1.w * q[1].w
               + t2.x * q[2].x + t2.y * q[2].y + t2.z * q[2].z + t2.w * q[2].w
               + t3.x * q[3].x + t3.y * q[3].y + t3.z * q[3].z + t3.w * q[3].w;
            dt = t0.x * t0.x + t0.y * t0.y + t0.z * t0.z + t0.w * t0.w
               + t1.x * t1.x + t1.y * t1.y + t1.z * t1.z + t1.w * t1.w
               + t2.x * t2.x + t2.y * t2.y + t2.z * t2.z + t2.w * t2.w
               + t3.x * t3.x + t3.y * t3.y + t3.z * t3.z + t3.w * t3.w;
        }

        // 4-level reduce within each 16-lane half (both halves in parallel)
        #pragma unroll
        for (int o = 8; o > 0; o >>= 1) {
            dq += __shfl_xor_sync(FULL, dq, o);
            dt += __shfl_xor_sync(FULL, dt, o);
        }

        // s = dot(t,q)/||t||/(||q||+eps); the reference's inner renormalize
        // (||u||+eps, ||u||~=1) perturbs s by ~1e-7 << tolerance. TAO = 1.0.
        if (live && sub == 0) {
            const float e = expf(dq * rsqrtf(dt) * invq);
            if ((posmask >> bit) & 1u) psum += e;
            if ((negmask >> bit) & 1u) nsum += e;
        }
    }

    // Merge the two halves (only lanes 0 and 16 hold nonzero sums)
    psum += __shfl_xor_sync(FULL, psum, 16);
    nsum += __shfl_xor_sync(FULL, nsum, 16);

    // Block reduction -> per-block partial (unconditional write: no init pass)
    __shared__ float s_p[8];
    __shared__ float s_n[8];
    if (lane == 0) { s_p[wid] = psum; s_n[wid] = nsum; }
    __syncthreads();
    if (threadIdx.x == 0) {
        float ap = 0.0f, an = 0.0f;
        #pragma unroll
        for (int i = 0; i < 8; i++) { ap += s_p[i]; an += s_n[i]; }
        g_part_p[blockIdx.x] = ap;
        g_part_n[blockIdx.x] = an;
    }
}

// ---------------------------------------------------------------------------
// Kernel 2: final loss. 1 block, 256 threads.
// Warp w handles batches w, w+8, w+16, w+24; lane reads one block partial
// (batch b's partials live at g_part_*[b*32 .. b*32+31]).
// valid(b) = nonempty pos & neg sets <=> both sums > 0 (exp > 0).
// ---------------------------------------------------------------------------
__global__ void __launch_bounds__(256) cl_final_kernel(float* __restrict__ out) {
    const int wid  = threadIdx.x >> 5;
    const int lane = threadIdx.x & 31;

    float li_acc = 0.0f;
    int   v_acc  = 0;
    #pragma unroll
    for (int r = 0; r < 4; r++) {
        const int bb = wid + r * 8;
        float p = g_part_p[bb * 32 + lane];
        float n = g_part_n[bb * 32 + lane];
        #pragma unroll
        for (int o = 16; o > 0; o >>= 1) {
            p += __shfl_xor_sync(FULL, p, o);
            n += __shfl_xor_sync(FULL, n, o);
        }
        if (lane == 0 && p > 0.0f && n > 0.0f) {
            li_acc += -logf(p / (p + n + EPSF));
            v_acc  += 1;
        }
    }

    __shared__ float s_li[8];
    __shared__ int   s_v[8];
    if (lane == 0) { s_li[wid] = li_acc; s_v[wid] = v_acc; }
    __syncthreads();
    if (threadIdx.x == 0) {
        float li = 0.0f; int v = 0;
        #pragma unroll
        for (int i = 0; i < 8; i++) { li += s_li[i]; v += s_v[i]; }
        out[0] = li / (float)(v > 0 ? v : 1);
    }
}

// ---------------------------------------------------------------------------
// Launch. Input order (metadata / setup_inputs dict order):
//   d_in[0] = pos_query  (B,H)     float32
//   d_in[1] = tmap       (B,S,S,H) float32
//   d_in[2] = mask2d_pos (B,S,S)   bool -> int32
//   d_in[3] = mask2d_neg (B,S,S)   bool -> int32
// Output: scalar float32.
// ---------------------------------------------------------------------------
extern "C" void kernel_launch(void* const* d_in, const int* in_sizes, int n_in,
                              void* d_out, int out_size) {
    (void)in_sizes; (void)n_in; (void)out_size;
    const float* pos_query = (const float*)d_in[0];
    const float* tmap      = (const float*)d_in[1];
    const int*   mpos      = (const int*)d_in[2];
    const int*   mneg      = (const int*)d_in[3];
    float*       out       = (float*)d_out;

    cl_main_kernel<<<NBLOCKS, 256>>>(tmap, pos_query, mpos, mneg);
    cl_final_kernel<<<1, 256>>>(out);
}

// round 17
// speedup vs baseline: 1.0381x; 1.0173x over previous
#include <cuda_runtime.h>
#include <math.h>

// Problem constants (fixed shapes from reference setup_inputs)
#define BB 32
#define SS 64
#define HH 256
#define CELLS_PER_BATCH (SS * SS)   // 4096
#define NBLOCKS (BB * 32)           // 1024: 32 blocks per batch
#define EPSF 1e-8f
#define FULL 0xFFFFFFFFu

// Per-block partial sums. Written unconditionally by every block every launch,
// so they never need zero-initialization (graph-replay safe).
__device__ float g_part_p[NBLOCKS];
__device__ float g_part_n[NBLOCKS];

// ---------------------------------------------------------------------------
// Kernel 1: main reduction. Half-warp-per-cell + ballot-compacted live loop.
//   grid = 1024 blocks x 256 threads; block bi -> batch bi>>5;
//   warp w owns 16 consecutive cells.
//   - masks for all 16 cells read up front (1 lane each) -> 16-bit bitmaps;
//     the compacted loop body has NO load->branch dependence, so consecutive
//     pairs' tmap loads can be batched by the compiler (high MLP).
//   - each 16-lane half processes one live cell: 4 LDG.128 in flight,
//     4-level shuffle reduce.
//   - invq computed per-warp from q registers (no init kernel).
// ---------------------------------------------------------------------------
__global__ void __launch_bounds__(256) cl_main_kernel(
    const float* __restrict__ tmap,
    const float* __restrict__ pos_query,
    const int*   __restrict__ mpos,
    const int*   __restrict__ mneg)
{
    const int b        = blockIdx.x >> 5;        // 32 blocks per batch
    const int blk_in_b = blockIdx.x & 31;
    const int wid      = threadIdx.x >> 5;
    const int lane     = threadIdx.x & 31;
    const int half     = lane >> 4;              // which cell of each live pair
    const int sub      = lane & 15;              // lane within the half

    const int cell0 = b * CELLS_PER_BATCH + blk_in_b * 128 + wid * 16;

    // Query: each half covers the FULL 256-dim vector (16 lanes x 4 float4).
    const float4* qp = reinterpret_cast<const float4*>(pos_query + (size_t)b * HH);
    float4 q[4];
    #pragma unroll
    for (int j = 0; j < 4; j++) q[j] = qp[sub + 16 * j];

    // invq = 1/(||q||+eps): reduce within the half (covers whole vector)
    float qq = 0.0f;
    #pragma unroll
    for (int j = 0; j < 4; j++)
        qq += q[j].x * q[j].x + q[j].y * q[j].y + q[j].z * q[j].z + q[j].w * q[j].w;
    #pragma unroll
    for (int o = 8; o > 0; o >>= 1)
        qq += __shfl_xor_sync(FULL, qq, o);
    const float invq = 1.0f / (sqrtf(qq) + EPSF);

    // Read all 16 cell masks up front: lane k (k<16) covers cell0+k.
    int pmv = 0, nmv = 0;
    if (lane < 16) {
        pmv = mpos[cell0 + lane];
        nmv = mneg[cell0 + lane];
    }
    const unsigned posmask = __ballot_sync(FULL, pmv != 0);   // bits 0..15 only
    const unsigned negmask = __ballot_sync(FULL, nmv != 0);
    const unsigned livemask = posmask | negmask;
    const int nlive  = __popc(livemask);
    const int npairs = (nlive + 1) >> 1;

    float psum = 0.0f, nsum = 0.0f;

    #pragma unroll 2
    for (int i = 0; i < npairs; i++) {
        const int ord  = 2 * i + half;                     // which live cell (ordinal)
        const bool live = (ord < nlive);
        const unsigned bitpos = __fns(livemask, 0, ord + 1);  // 0xFFFFFFFF if none
        const int bit  = (int)(bitpos & 15u);              // safe index even if dead
        const int c    = cell0 + bit;

        float dq = 0.0f, dt = 1.0f;
        if (live) {
            const float4* tp = reinterpret_cast<const float4*>(tmap + (size_t)c * HH);
            float4 t0 = tp[sub];
            float4 t1 = tp[sub + 16];
            float4 t2 = tp[sub + 32];
            float4 t3 = tp[sub + 48];
            dq = t0.x * q[0].x + t0.y * q[0].y + t0.z * q[0].z + t0.w * q[0].w
               + t1.x * q[1].x + t1.y * q[1].y + t1.z * q[1].z + t1.w * q[1].w
               + t2.x * q[2].x + t2.y * q[2].y + t2.z * q[2].z + t2.w * q[2].w
               + t3.x * q[3].x + t3.y * q[3].y + t3.z * q[3].z + t3.w * q[3].w;
            dt = t0.x * t0.x + t0.y * t0.y + t0.z * t0.z + t0.w * t0.w
               + t1.x * t1.x + t1.y * t1.y + t1.z * t1.z + t1.w * t1.w
               + t2.x * t2.x + t2.y * t2.y + t2.z * t2.z + t2.w * t2.w
               + t3.x * t3.x + t3.y * t3.y + t3.z * t3.z + t3.w * t3.w;
        }

        // 4-level reduce within each 16-lane half (both halves in parallel)
        #pragma unroll
        for (int o = 8; o > 0; o >>= 1) {
            dq += __shfl_xor_sync(FULL, dq, o);
            dt += __shfl_xor_sync(FULL, dt, o);
        }

        // s = dot(t,q)/||t||/(||q||+eps); the reference's inner renormalize
        // (||u||+eps, ||u||~=1) perturbs s by ~1e-7 << tolerance. TAO = 1.0.
        if (live && sub == 0) {
            const float e = expf(dq * rsqrtf(dt) * invq);
            if ((posmask >> bit) & 1u) psum += e;
            if ((negmask >> bit) & 1u) nsum += e;
        }
    }

    // Merge the two halves (only lanes 0 and 16 hold nonzero sums)
    psum += __shfl_xor_sync(FULL, psum, 16);
    nsum += __shfl_xor_sync(FULL, nsum, 16);

    // Block reduction -> per-block partial (unconditional write: no init pass)
    __shared__ float s_p[8];
    __shared__ float s_n[8];
    if (lane == 0) { s_p[wid] = psum; s_n[wid] = nsum; }
    __syncthreads();
    if (threadIdx.x == 0) {
        float ap = 0.0f, an = 0.0f;
        #pragma unroll
        for (int i = 0; i < 8; i++) { ap += s_p[i]; an += s_n[i]; }
        g_part_p[blockIdx.x] = ap;
        g_part_n[blockIdx.x] = an;
    }
}

// ---------------------------------------------------------------------------
// Kernel 2: final loss. 1 block, 256 threads.
// Warp w handles batches w, w+8, w+16, w+24; lane reads one block partial
// (batch b's partials live at g_part_*[b*32 .. b*32+31]).
// valid(b) = nonempty pos & neg sets <=> both sums > 0 (exp > 0).
// ---------------------------------------------------------------------------
__global__ void __launch_bounds__(256) cl_final_kernel(float* __restrict__ out) {
    const int wid  = threadIdx.x >> 5;
    const int lane = threadIdx.x & 31;

    float li_acc = 0.0f;
    int   v_acc  = 0;
    #pragma unroll
    for (int r = 0; r < 4; r++) {
        const int bb = wid + r * 8;
        float p = g_part_p[bb * 32 + lane];
        float n = g_part_n[bb * 32 + lane];
        #pragma unroll
        for (int o = 16; o > 0; o >>= 1) {
            p += __shfl_xor_sync(FULL, p, o);
            n += __shfl_xor_sync(FULL, n, o);
        }
        if (lane == 0 && p > 0.0f && n > 0.0f) {
            li_acc += -logf(p / (p + n + EPSF));
            v_acc  += 1;
        }
    }

    __shared__ float s_li[8];
    __shared__ int   s_v[8];
    if (lane == 0) { s_li[wid] = li_acc; s_v[wid] = v_acc; }
    __syncthreads();
    if (threadIdx.x == 0) {
        float li = 0.0f; int v = 0;
        #pragma unroll
        for (int i = 0; i < 8; i++) { li += s_li[i]; v += s_v[i]; }
        out[0] = li / (float)(v > 0 ? v : 1);
    }
}

// ---------------------------------------------------------------------------
// Launch. Input order (metadata / setup_inputs dict order):
//   d_in[0] = pos_query  (B,H)     float32
//   d_in[1] = tmap       (B,S,S,H) float32
//   d_in[2] = mask2d_pos (B,S,S)   bool -> int32
//   d_in[3] = mask2d_neg (B,S,S)   bool -> int32
// Output: scalar float32.
// ---------------------------------------------------------------------------
extern "C" void kernel_launch(void* const* d_in, const int* in_sizes, int n_in,
                              void* d_out, int out_size) {
    (void)in_sizes; (void)n_in; (void)out_size;
    const float* pos_query = (const float*)d_in[0];
    const float* tmap      = (const float*)d_in[1];
    const int*   mpos      = (const int*)d_in[2];
    const int*   mneg      = (const int*)d_in[3];
    float*       out       = (float*)d_out;

    cl_main_kernel<<<NBLOCKS, 256>>>(tmap, pos_query, mpos, mneg);
    cl_final_kernel<<<1, 256>>>(out);
}